// round 12
// baseline (speedup 1.0000x reference)
#include <cuda_runtime.h>
#include <cuda_fp16.h>
#include <cstdint>

// ---------------------------------------------------------------------------
// DCGN collapses (normalized adjacency == identity) to:
//   g1 = node_conv(x, conv1_w)                [8192, 2048]
//   h  = lrelu(g1 @ prop1_W + prop1_B)        [8192, 1100]  (N pad -> 1152)
//   g2 = node_conv(h, conv2_w)                [2048, 1100]  (K pad -> 1152)
//   out= lrelu(g2 @ prop2_W + prop2_B)        [2048, 512]
// fp16 x fp16 mma.sync GEMMs (measured error budget ~3e-5).
// 3 launches: prep (transposes + nodeconv1 merged) -> GEMM1 (nodeconv2 fused
// in epilogue; h never exists) -> GEMM2.
// ---------------------------------------------------------------------------

#define ROWS1 8192
#define F1    2048
#define N1R   1100
#define N1P   1152
#define ROWS2 2048
#define K2P   1152
#define N2    512

__device__ __half g_g1[(size_t)ROWS1 * F1];
__device__ __half g_g2[(size_t)ROWS2 * K2P];
__device__ __half g_w1[(size_t)N1P * F1];
__device__ __half g_w2[(size_t)N2 * K2P];

// ===================== PTX helpers ========================

__device__ __forceinline__ uint32_t smem_u32(const void* p) {
    uint32_t a;
    asm("{ .reg .u64 t; cvta.to.shared.u64 t, %1; cvt.u32.u64 %0, t; }"
        : "=r"(a) : "l"(p));
    return a;
}

__device__ __forceinline__ void cp16(uint32_t dst, const void* src) {
    asm volatile("cp.async.cg.shared.global [%0], [%1], 16;"
                 :: "r"(dst), "l"(src));
}

__device__ __forceinline__ void ldm_x4(uint32_t* r, uint32_t addr) {
    asm volatile("ldmatrix.sync.aligned.m8n8.x4.shared.b16 {%0,%1,%2,%3}, [%4];"
                 : "=r"(r[0]), "=r"(r[1]), "=r"(r[2]), "=r"(r[3]) : "r"(addr));
}

__device__ __forceinline__ void mma16816(float* c, const uint32_t* a,
                                         const uint32_t* b) {
    asm volatile(
        "mma.sync.aligned.m16n8k16.row.col.f32.f16.f16.f32 "
        "{%0,%1,%2,%3}, {%4,%5,%6,%7}, {%8,%9}, {%0,%1,%2,%3};"
        : "+f"(c[0]), "+f"(c[1]), "+f"(c[2]), "+f"(c[3])
        : "r"(a[0]), "r"(a[1]), "r"(a[2]), "r"(a[3]), "r"(b[0]), "r"(b[1]));
}

// swizzled byte offset inside a 128-row x 32-col fp16 tile (64B rows)
__device__ __forceinline__ uint32_t swz(uint32_t row, uint32_t chunk) {
    return row * 64u + ((chunk ^ ((row >> 1) & 3u)) << 4);
}

__device__ __forceinline__ float lrelu(float v) {
    return (v >= 0.f) ? v : 0.01f * v;
}

// ======================= fused prep kernel ==================================
// blocks [0, n1blocks):              transpose prop1_W -> w1 (fp16, padded)
// blocks [n1blocks, n1+n2):          transpose prop2_W -> w2
// blocks [n1+n2, ...):               nodeconv1: g1 = fp16(node_conv(x, conv1_w))
// all blocks: 256 threads.

__global__ void prep_kernel(const float* __restrict__ W1, __half* __restrict__ B1,
                            int n1bx, int n1blocks,
                            const float* __restrict__ W2, __half* __restrict__ B2,
                            int n2bx, int n2blocks,
                            const float* __restrict__ x,
                            const float* __restrict__ cw1,  // [4, F1]
                            __half* __restrict__ g1)
{
    const int b = blockIdx.x;
    const int tid = threadIdx.x;

    if (b < n1blocks + n2blocks) {
        // ---- transpose path ----
        __shared__ float tile[32][33];
        const float* W; __half* Bo;
        int Kreal, Kpad, Nreal, Npad, bb, bx;
        if (b < n1blocks) {
            W = W1; Bo = B1; Kreal = F1; Kpad = F1; Nreal = N1R; Npad = N1P;
            bx = b % n1bx; bb = b / n1bx;
        } else {
            int b2 = b - n1blocks;
            W = W2; Bo = B2; Kreal = N1R; Kpad = K2P; Nreal = N2; Npad = N2;
            bx = b2 % n2bx; bb = b2 / n2bx;
        }
        const int nb = bx * 32, kb = bb * 32;
        const int tx = tid & 31, ty = tid >> 5;   // (32, 8)
#pragma unroll
        for (int i = 0; i < 32; i += 8) {
            int k = kb + ty + i, n = nb + tx;
            tile[ty + i][tx] =
                (k < Kreal && n < Nreal) ? W[(size_t)k * Nreal + n] : 0.f;
        }
        __syncthreads();
#pragma unroll
        for (int i = 0; i < 32; i += 8) {
            int n = nb + ty + i, k = kb + tx;
            if (n < Npad && k < Kpad)
                Bo[(size_t)n * Kpad + k] = __float2half_rn(tile[tx][ty + i]);
        }
        return;
    }

    // ---- nodeconv1 path ----
    const int idx = (b - n1blocks - n2blocks) * 256 + tid;
    const int K4 = F1 >> 2;
    if (idx >= ROWS1 * K4) return;
    const int r = idx / K4;
    const int c = (idx - r * K4) << 2;

    float acc[4] = {0.f, 0.f, 0.f, 0.f};
#pragma unroll
    for (int p = 0; p < 4; ++p) {
        float4 xv = *(const float4*)(x + (size_t)(4 * r + p) * F1 + c);
        float4 wv = *(const float4*)(cw1 + (size_t)p * F1 + c);
        acc[0] = fmaf(xv.x, wv.x, acc[0]);
        acc[1] = fmaf(xv.y, wv.y, acc[1]);
        acc[2] = fmaf(xv.z, wv.z, acc[2]);
        acc[3] = fmaf(xv.w, wv.w, acc[3]);
    }
    __align__(8) __half hv[4];
#pragma unroll
    for (int i = 0; i < 4; ++i) hv[i] = __float2half_rn(acc[i]);
    *(uint2*)(g1 + (size_t)r * F1 + c) = *(uint2*)hv;
}

// ======================= fp16 mma.sync GEMM ================================
// CTA tile: 128 x 128, 128 threads (4 warps of 64x64), 4-stage cp.async.
// EPI == 0: C float, C = lrelu(A @ B^T + bias)
// EPI == 2: fused nodeconv epilogue:
//           g2[r,col] = sum_p lrelu((A@B^T+bias)[4r+p,col]) * cw[p,col]
// grid = (Npad/128, M/128), K % 32 == 0, K/32 >= 4.

#define BK       32
#define STAGES   4
#define TILE_B   8192                   // one 128x32 fp16 tile
#define STAGE_B  (2 * TILE_B)           // A + B
#define SMEM_DYN (STAGES * STAGE_B)     // 65536

template <int EPI>
__global__ __launch_bounds__(128, 2)
void gemm_fp16(const __half* __restrict__ A,
               const __half* __restrict__ B,
               const float* __restrict__ bias,
               void* __restrict__ Cv,
               const float* __restrict__ cw,   // [4, Nreal] (EPI==2 only)
               int K, int Nreal, int ostride)
{
    extern __shared__ __align__(1024) char smem[];
    const uint32_t sb = smem_u32(smem);

    const int tid  = threadIdx.x;
    const int wid  = tid >> 5;
    const int lane = tid & 31;
    const int row0 = blockIdx.y * 128;
    const int col0 = blockIdx.x * 128;
    const int NC   = K / BK;

    const int warp_m = (wid & 1) * 64;     // 2 warps in M
    const int warp_n = (wid >> 1) * 64;    // 2 warps in N

    // ---- cp.async mapping: thread covers 4 chunks per 128x32 tile ----
    uint32_t ssw[4];
    int      srow[4];
#pragma unroll
    for (int q = 0; q < 4; ++q) {
        const int idx = tid + q * 128;      // 0..511
        srow[q] = idx >> 2;
        ssw[q]  = swz(idx >> 2, idx & 3);
    }
    const int schk = tid & 3;

    auto issue_stage = [&](int st, int kt) {
        const int kb = kt * BK + schk * 8;
        const uint32_t base = sb + st * STAGE_B;
#pragma unroll
        for (int q = 0; q < 4; ++q) {
            cp16(base + ssw[q],          A + (size_t)(row0 + srow[q]) * K + kb);
            cp16(base + TILE_B + ssw[q], B + (size_t)(col0 + srow[q]) * K + kb);
        }
        asm volatile("cp.async.commit_group;");
    };

    float acc[4][8][4];
#pragma unroll
    for (int mt = 0; mt < 4; ++mt)
#pragma unroll
        for (int nt = 0; nt < 8; ++nt)
#pragma unroll
            for (int q = 0; q < 4; ++q) acc[mt][nt][q] = 0.f;

    issue_stage(0, 0);
    issue_stage(1, 1);
    issue_stage(2, 2);

    // ldmatrix lane-dependent pieces
    const uint32_t a_lrow = lane & 15;
    const uint32_t a_lchk = lane >> 4;
    const uint32_t b_lrow = (lane & 7) + ((lane >> 4) << 3);
    const uint32_t b_lchk = (lane >> 3) & 1;

    for (int i = 0; i < NC; ++i) {
        asm volatile("cp.async.wait_group 2;");
        __syncthreads();
        if (i + 3 < NC) issue_stage((i + 3) & 3, i + 3);

        const uint32_t base = sb + (i & 3) * STAGE_B;

        // ---- load ALL B fragments (both ks halves) up front ----
        uint32_t bfr[2][8][2];
#pragma unroll
        for (int ks = 0; ks < 2; ++ks)
#pragma unroll
            for (int ntp = 0; ntp < 4; ++ntp)
                ldm_x4(&bfr[ks][ntp * 2][0],
                       base + TILE_B +
                       swz(warp_n + ntp * 16 + b_lrow, ks * 2 + b_lchk));

        // ---- A fragments: double-buffered one step ahead ----
        uint32_t afr[2][4];
        ldm_x4(afr[0], base + swz(warp_m + a_lrow, a_lchk));
#pragma unroll
        for (int ks = 0; ks < 2; ++ks) {
#pragma unroll
            for (int mt = 0; mt < 4; ++mt) {
                const int step = ks * 4 + mt;
                const int cur  = step & 1;
                if (step < 7) {
                    const int nmt = (mt + 1) & 3;
                    const int nks = ks + (mt == 3 ? 1 : 0);
                    ldm_x4(afr[cur ^ 1],
                           base + swz(warp_m + nmt * 16 + a_lrow,
                                      nks * 2 + a_lchk));
                }
#pragma unroll
                for (int nt = 0; nt < 8; ++nt)
                    mma16816(acc[mt][nt], afr[cur], bfr[ks][nt]);
            }
        }
        // stage-reuse ordering is provided by the top-of-loop barrier
    }

    // ---- epilogue ----
    const int erow = lane >> 2;          // 0..7
    const int ecol = (lane & 3) * 2;

    if constexpr (EPI == 0) {
        float* C = (float*)Cv;
#pragma unroll
        for (int mt = 0; mt < 4; ++mt) {
#pragma unroll
            for (int nt = 0; nt < 8; ++nt) {
                const int colg = col0 + warp_n + nt * 8 + ecol;
                if (colg >= Nreal) continue;
                const float bx = bias[colg], by = bias[colg + 1];
                const int rg0 = row0 + warp_m + mt * 16 + erow;
                float v0 = lrelu(acc[mt][nt][0] + bx);
                float v1 = lrelu(acc[mt][nt][1] + by);
                float v2 = lrelu(acc[mt][nt][2] + bx);
                float v3 = lrelu(acc[mt][nt][3] + by);
                *(float2*)(C + (size_t)rg0 * ostride + colg) =
                    make_float2(v0, v1);
                *(float2*)(C + (size_t)(rg0 + 8) * ostride + colg) =
                    make_float2(v2, v3);
            }
        }
    } else {
        // fused nodeconv2: reduce lrelu(h) over 4-row windows with weights
        // cw[p, col], p = erow & 3 (row0+warp_m+mt*16 is a multiple of 4)
        __half* C = (__half*)Cv;
        const int p = erow & 3;
        const bool writer = ((erow & 3) == 0);
        const int sub = (lane >> 4);
#pragma unroll
        for (int nt = 0; nt < 8; ++nt) {
            const int colg = col0 + warp_n + nt * 8 + ecol;
            float bx = 0.f, by = 0.f, cwx = 0.f, cwy = 0.f;
            if (colg < Nreal) {
                bx  = bias[colg];
                by  = bias[colg + 1];
                cwx = cw[(size_t)p * Nreal + colg];
                cwy = cw[(size_t)p * Nreal + colg + 1];
            }
#pragma unroll
            for (int mt = 0; mt < 4; ++mt) {
                float s0 = lrelu(acc[mt][nt][0] + bx) * cwx;
                float s1 = lrelu(acc[mt][nt][1] + by) * cwy;
                float s2 = lrelu(acc[mt][nt][2] + bx) * cwx;
                float s3 = lrelu(acc[mt][nt][3] + by) * cwy;
                s0 += __shfl_xor_sync(0xffffffffu, s0, 4);
                s0 += __shfl_xor_sync(0xffffffffu, s0, 8);
                s1 += __shfl_xor_sync(0xffffffffu, s1, 4);
                s1 += __shfl_xor_sync(0xffffffffu, s1, 8);
                s2 += __shfl_xor_sync(0xffffffffu, s2, 4);
                s2 += __shfl_xor_sync(0xffffffffu, s2, 8);
                s3 += __shfl_xor_sync(0xffffffffu, s3, 4);
                s3 += __shfl_xor_sync(0xffffffffu, s3, 8);
                if (writer) {
                    const int g2r = ((row0 + warp_m + mt * 16) >> 2) + sub;
                    *(__half2*)(C + (size_t)g2r * ostride + colg) =
                        __floats2half2_rn(s0, s1);
                    *(__half2*)(C + (size_t)(g2r + 2) * ostride + colg) =
                        __floats2half2_rn(s2, s3);
                }
            }
        }
    }
}

// ======================= launch ============================================

extern "C" void kernel_launch(void* const* d_in, const int* in_sizes, int n_in,
                              void* d_out, int out_size)
{
    const float* x       = (const float*)d_in[0];   // [64,512,2048]
    const float* conv1_w = (const float*)d_in[1];   // [4,2048]
    const float* prop1_W = (const float*)d_in[4];   // [2048,1100]
    const float* prop1_B = (const float*)d_in[5];   // [1100]
    const float* conv2_w = (const float*)d_in[6];   // [4,1100]
    const float* prop2_W = (const float*)d_in[9];   // [1100,512]
    const float* prop2_B = (const float*)d_in[10];  // [512]

    __half *g1, *g2, *w1, *w2;
    cudaGetSymbolAddress((void**)&g1, g_g1);
    cudaGetSymbolAddress((void**)&g2, g_g2);
    cudaGetSymbolAddress((void**)&w1, g_w1);
    cudaGetSymbolAddress((void**)&w2, g_w2);

    cudaFuncSetAttribute((void*)gemm_fp16<2>,
                         cudaFuncAttributeMaxDynamicSharedMemorySize, SMEM_DYN);
    cudaFuncSetAttribute((void*)gemm_fp16<0>,
                         cudaFuncAttributeMaxDynamicSharedMemorySize, SMEM_DYN);

    // 1) prep: both weight transposes + nodeconv1 in ONE launch
    {
        const int n1bx = N1P / 32, n1blocks = n1bx * (F1 / 32);   // 36*64=2304
        const int n2bx = N2 / 32,  n2blocks = n2bx * (K2P / 32);  // 16*36=576
        const int ncblocks = (ROWS1 * (F1 / 4) + 255) / 256;      // 16384
        prep_kernel<<<n1blocks + n2blocks + ncblocks, 256>>>(
            prop1_W, w1, n1bx, n1blocks,
            prop2_W, w2, n2bx, n2blocks,
            x, conv1_w, g1);
    }

    // 2) GEMM1 with fused nodeconv2 -> writes g2
    gemm_fp16<2><<<dim3(N1P / 128, ROWS1 / 128), 128, SMEM_DYN>>>(
        g1, w1, prop1_B, g2, conv2_w, F1, N1R, K2P);

    // 3) GEMM2 -> final output
    gemm_fp16<0><<<dim3(N2 / 128, ROWS2 / 128), 128, SMEM_DYN>>>(
        g2, w2, prop2_B, d_out, nullptr, K2P, N2, N2);
}